// round 5
// baseline (speedup 1.0000x reference)
#include <cuda_runtime.h>

#define NN   50000
#define FEAT 64
#define F4   16
#define LL   4
#define NNZ  800000
#define STRIDE 64                 // fixed slab per row/col (max degree guard)

#define NODE_THREADS (NN * F4)    // 800000
#define WARP_THREADS (NN * 32)    // 1600000

// ---------------- persistent scratch (rebuilt every call) ----------------
__device__ float4 g_Uk [NN * F4];
__device__ float4 g_Lam[3][NN * F4];          // operators 1..3 only (Lam0 == 0)
__device__ float4 g_tmp[LL][NN * F4];
__device__ float4 g_agg[NN * F4];

__device__ int    g_rcnt[NN];
__device__ int    g_ccnt[NN];
__device__ int    g_csr_col[NN * STRIDE];
__device__ float4 g_csr_w  [NN * STRIDE];
__device__ int    g_csc_row[NN * STRIDE];
__device__ float4 g_csc_w  [NN * STRIDE];

// ---------------------------------------------------------------------------
// Setup: zero counters, then single scatter pass builds CSR + CSC slabs.
// ---------------------------------------------------------------------------
__global__ __launch_bounds__(256) void k_zero() {
    int i = blockIdx.x * blockDim.x + threadIdx.x;
    if (i < NN) { g_rcnt[i] = 0; g_ccnt[i] = 0; }
}

__global__ __launch_bounds__(256) void k_scatter(const int*   __restrict__ rows,
                                                 const int*   __restrict__ cols,
                                                 const float* __restrict__ w) {
    int e = blockIdx.x * blockDim.x + threadIdx.x;
    if (e >= NNZ) return;
    int r = __ldg(&rows[e]);
    int c = __ldg(&cols[e]);
    float4 w4 = make_float4(__ldg(&w[e]),
                            __ldg(&w[NNZ + e]),
                            __ldg(&w[2 * NNZ + e]),
                            __ldg(&w[3 * NNZ + e]));
    int p = atomicAdd(&g_rcnt[r], 1);
    if (p < STRIDE) {
        g_csr_col[r * STRIDE + p] = c;
        g_csr_w  [r * STRIDE + p] = w4;
    }
    int q = atomicAdd(&g_ccnt[c], 1);
    if (q < STRIDE) {
        g_csc_row[c * STRIDE + q] = r;
        g_csc_w  [c * STRIDE + q] = w4;
    }
}

// ---------------------------------------------------------------------------
// Iter 0: Uk = d/(d+1) * x ; Lam = 0 ; agg = 0
// ---------------------------------------------------------------------------
__global__ __launch_bounds__(256) void k_init(const float4* __restrict__ x,
                                              const float*  __restrict__ d) {
    int i = blockIdx.x * blockDim.x + threadIdx.x;
    if (i >= NODE_THREADS) return;
    int n = i >> 4;
    float dn = __ldg(&d[n]);
    float s = dn / (dn + 1.0f);
    float4 xv = __ldg(&x[i]);
    g_Uk[i] = make_float4(s * xv.x, s * xv.y, s * xv.z, s * xv.w);
    float4 z = make_float4(0.f, 0.f, 0.f, 0.f);
#pragma unroll
    for (int l = 0; l < 3; l++) g_Lam[l][i] = z;
    g_agg[i] = z;
}

// ---------------------------------------------------------------------------
// WU_l = W_l @ Uk  (warp per row; even/odd edge split; pipelined gather)
// fused with Q / dual / tmp updates.  Lam0==0, Q0==WU0, tmp0 = mu2n*WU0.
// ---------------------------------------------------------------------------
__global__ __launch_bounds__(256) void k_wu_q(const float* __restrict__ d,
                                              float mu2, float inv_mu2, float mu2n) {
    int t = blockIdx.x * blockDim.x + threadIdx.x;
    if (t >= WARP_THREADS) return;
    int row  = t >> 5;
    int lane = t & 31;
    int c    = lane & 15;
    int eo   = lane >> 4;
    int cnt  = g_rcnt[row];
    int base = row * STRIDE;

    float4 wu[LL];
#pragma unroll
    for (int l = 0; l < LL; l++) wu[l] = make_float4(0.f, 0.f, 0.f, 0.f);

    int k = eo;
    int col = 0; float4 wv = make_float4(0.f, 0.f, 0.f, 0.f);
    if (k < cnt) { col = g_csr_col[base + k]; wv = g_csr_w[base + k]; }
    while (k < cnt) {
        int kn = k + 2;
        int coln = 0; float4 wvn = wv;
        if (kn < cnt) { coln = g_csr_col[base + kn]; wvn = g_csr_w[base + kn]; }
        float4 u = g_Uk[col * F4 + c];
        wu[0].x += wv.x * u.x; wu[0].y += wv.x * u.y; wu[0].z += wv.x * u.z; wu[0].w += wv.x * u.w;
        wu[1].x += wv.y * u.x; wu[1].y += wv.y * u.y; wu[1].z += wv.y * u.z; wu[1].w += wv.y * u.w;
        wu[2].x += wv.z * u.x; wu[2].y += wv.z * u.y; wu[2].z += wv.z * u.z; wu[2].w += wv.z * u.w;
        wu[3].x += wv.w * u.x; wu[3].y += wv.w * u.y; wu[3].z += wv.w * u.z; wu[3].w += wv.w * u.w;
        col = coln; wv = wvn; k = kn;
    }

    // combine the even/odd halves (lane ^ 16 holds the other partial sum)
#pragma unroll
    for (int l = 0; l < LL; l++) {
        wu[l].x += __shfl_xor_sync(0xffffffffu, wu[l].x, 16);
        wu[l].y += __shfl_xor_sync(0xffffffffu, wu[l].y, 16);
        wu[l].z += __shfl_xor_sync(0xffffffffu, wu[l].z, 16);
        wu[l].w += __shfl_xor_sync(0xffffffffu, wu[l].w, 16);
    }

    if (eo != 0) return;      // lower half-warp writes the epilogue

    int i = row * F4 + c;
    // operator 0: nu=0 -> Q0 = WU0, Lam0 stays 0, tmp0 = mu2n * WU0
    g_tmp[0][i] = make_float4(mu2n * wu[0].x, mu2n * wu[0].y,
                              mu2n * wu[0].z, mu2n * wu[0].w);

    const float nu_i[3] = {1.0f, 0.25f, 0.0625f};
    float dn = __ldg(&d[row]);
#pragma unroll
    for (int l = 0; l < 3; l++) {
        float4 wul = wu[l + 1];
        float4 lam = g_Lam[l][i];
        float eta = nu_i[l] * inv_mu2 * dn;
        float4 q, lam2, tv;
        float xm;
        xm = wul.x - lam.x * inv_mu2;
        q.x = fmaxf(xm - eta, 0.f) - fmaxf(-xm - eta, 0.f);
        xm = wul.y - lam.y * inv_mu2;
        q.y = fmaxf(xm - eta, 0.f) - fmaxf(-xm - eta, 0.f);
        xm = wul.z - lam.z * inv_mu2;
        q.z = fmaxf(xm - eta, 0.f) - fmaxf(-xm - eta, 0.f);
        xm = wul.w - lam.w * inv_mu2;
        q.w = fmaxf(xm - eta, 0.f) - fmaxf(-xm - eta, 0.f);
        lam2.x = lam.x + mu2 * (q.x - wul.x);
        lam2.y = lam.y + mu2 * (q.y - wul.y);
        lam2.z = lam.z + mu2 * (q.z - wul.z);
        lam2.w = lam.w + mu2 * (q.w - wul.w);
        tv.x = mu2n * q.x + lam2.x;
        tv.y = mu2n * q.y + lam2.y;
        tv.z = mu2n * q.z + lam2.z;
        tv.w = mu2n * q.w + lam2.w;
        g_Lam[l][i]     = lam2;
        g_tmp[l + 1][i] = tv;
    }
}

// ---------------------------------------------------------------------------
// agg += Sum_l W_l @ tmp_l  (warp per col; even/odd split; pipelined; RED.v4)
// ---------------------------------------------------------------------------
__global__ __launch_bounds__(256) void k_agg_sc() {
    int t = blockIdx.x * blockDim.x + threadIdx.x;
    if (t >= WARP_THREADS) return;
    int col  = t >> 5;
    int lane = t & 31;
    int c    = lane & 15;
    int eo   = lane >> 4;
    int cnt  = g_ccnt[col];
    if (cnt == 0) return;
    int base = col * STRIDE;

    int o = col * F4 + c;
    float4 t0 = g_tmp[0][o];
    float4 t1 = g_tmp[1][o];
    float4 t2 = g_tmp[2][o];
    float4 t3 = g_tmp[3][o];

    int k = eo;
    int row = 0; float4 wv = make_float4(0.f, 0.f, 0.f, 0.f);
    if (k < cnt) { row = g_csc_row[base + k]; wv = g_csc_w[base + k]; }
    while (k < cnt) {
        int kn = k + 2;
        int rown = 0; float4 wvn = wv;
        if (kn < cnt) { rown = g_csc_row[base + kn]; wvn = g_csc_w[base + kn]; }
        float4 v;
        v.x = wv.x * t0.x + wv.y * t1.x + wv.z * t2.x + wv.w * t3.x;
        v.y = wv.x * t0.y + wv.y * t1.y + wv.z * t2.y + wv.w * t3.y;
        v.z = wv.x * t0.z + wv.y * t1.z + wv.z * t2.z + wv.w * t3.z;
        v.w = wv.x * t0.w + wv.y * t1.w + wv.z * t2.w + wv.w * t3.w;
        atomicAdd(&g_agg[row * F4 + c], v);     // RED.E.ADD.F32.V4
        row = rown; wv = wvn; k = kn;
    }
}

// ---------------------------------------------------------------------------
// U update: Uk = (d*x + agg)/(d + mu2); re-zeroes agg for the next scatter.
// ---------------------------------------------------------------------------
__global__ __launch_bounds__(256) void k_u(const float4* __restrict__ x,
                                           const float*  __restrict__ d,
                                           float mu2, float4* outp) {
    int i = blockIdx.x * blockDim.x + threadIdx.x;
    if (i >= NODE_THREADS) return;
    int n = i >> 4;
    float dn = __ldg(&d[n]);
    float s = 1.0f / (dn + mu2);
    float4 a  = g_agg[i];
    float4 xv = __ldg(&x[i]);
    float4 r = make_float4(s * (dn * xv.x + a.x),
                           s * (dn * xv.y + a.y),
                           s * (dn * xv.z + a.z),
                           s * (dn * xv.w + a.w));
    if (outp) outp[i] = r;
    else      g_Uk[i] = r;
    g_agg[i] = make_float4(0.f, 0.f, 0.f, 0.f);
}

// ---------------------------------------------------------------------------
extern "C" void kernel_launch(void* const* d_in, const int* in_sizes, int n_in,
                              void* d_out, int out_size) {
    const float4* x    = (const float4*)d_in[0];
    const float*  w    = (const float*) d_in[1];
    const float*  d    = (const float*) d_in[2];
    const int*    rows = (const int*)   d_in[3];
    const int*    cols = (const int*)   d_in[4];

    const float mu2s[6] = {1.0f, 1.1f, 1.21f, 1.331f, 1.4641f, 1.61051f};

    const int NB_NODE = (NODE_THREADS + 255) / 256;  // 3125
    const int NB_WARP = (WARP_THREADS + 255) / 256;  // 6250
    const int NB_N    = (NN + 255) / 256;            // 196
    const int NB_E    = (NNZ + 255) / 256;           // 3125

    // ---- per-call CSR+CSC build (fixed-stride slabs; no hist/alloc) ----
    k_zero   <<<NB_N, 256>>>();
    k_scatter<<<NB_E, 256>>>(rows, cols, w);

    // ---- iteration 0 (Q=Lam=0 -> closed-form U) ----
    k_init<<<NB_NODE, 256>>>(x, d);
    k_wu_q<<<NB_WARP, 256>>>(d, mu2s[0], 1.0f / mu2s[0], mu2s[1]);

    // ---- iterations 1..4 (last: U update only, to d_out) ----
    for (int it = 1; it < 5; it++) {
        bool fin = (it == 4);
        k_agg_sc<<<NB_WARP, 256>>>();
        k_u<<<NB_NODE, 256>>>(x, d, mu2s[it], fin ? (float4*)d_out : (float4*)nullptr);
        if (!fin)
            k_wu_q<<<NB_WARP, 256>>>(d, mu2s[it], 1.0f / mu2s[it], mu2s[it + 1]);
    }
}

// round 7
// speedup vs baseline: 1.3711x; 1.3711x over previous
#include <cuda_runtime.h>

#define NN   50000
#define FEAT 64
#define F4   16
#define LL   4
#define NNZ  800000
#define STRIDE 64                 // fixed slab per row/col (max degree guard)

#define NODE_THREADS (NN * F4)    // 800000

// ---------------- persistent scratch (rebuilt every call) ----------------
__device__ float4 g_Uk [NN * F4];
__device__ float4 g_Lam[3][NN * F4];     // operators 1..3 only (Lam0 == 0)
__device__ float4 g_agg[NN * F4];

__device__ int    g_rcnt[NN];
__device__ int    g_ccnt[NN];
__device__ int    g_csr_col[NN * STRIDE];
__device__ float4 g_csr_w  [NN * STRIDE];
__device__ int    g_csc_row[NN * STRIDE];
__device__ float4 g_csc_w  [NN * STRIDE];

// ---------------------------------------------------------------------------
// Setup
// ---------------------------------------------------------------------------
__global__ __launch_bounds__(256) void k_zero() {
    int i = blockIdx.x * blockDim.x + threadIdx.x;
    if (i < NN) { g_rcnt[i] = 0; g_ccnt[i] = 0; }
}

// 4 edges per thread: vectorized index/weight loads, deep atomic MLP.
__global__ __launch_bounds__(256) void k_scatter(const int*   __restrict__ rows,
                                                 const int*   __restrict__ cols,
                                                 const float* __restrict__ w) {
    int e4 = (blockIdx.x * blockDim.x + threadIdx.x) * 4;
    if (e4 >= NNZ) return;
    int4   r4 = *(const int4*)(rows + e4);
    int4   c4 = *(const int4*)(cols + e4);
    float4 a  = *(const float4*)(w + e4);              // l=0
    float4 b  = *(const float4*)(w + NNZ + e4);        // l=1
    float4 cc = *(const float4*)(w + 2 * NNZ + e4);    // l=2
    float4 dd = *(const float4*)(w + 3 * NNZ + e4);    // l=3

    int    rr[4] = {r4.x, r4.y, r4.z, r4.w};
    int    cl[4] = {c4.x, c4.y, c4.z, c4.w};
    float4 w4[4] = {make_float4(a.x, b.x, cc.x, dd.x),
                    make_float4(a.y, b.y, cc.y, dd.y),
                    make_float4(a.z, b.z, cc.z, dd.z),
                    make_float4(a.w, b.w, cc.w, dd.w)};
#pragma unroll
    for (int j = 0; j < 4; j++) {
        int p = atomicAdd(&g_rcnt[rr[j]], 1);
        if (p < STRIDE) {
            g_csr_col[rr[j] * STRIDE + p] = cl[j];
            g_csr_w  [rr[j] * STRIDE + p] = w4[j];
        }
        int q = atomicAdd(&g_ccnt[cl[j]], 1);
        if (q < STRIDE) {
            g_csc_row[cl[j] * STRIDE + q] = rr[j];
            g_csc_w  [cl[j] * STRIDE + q] = w4[j];
        }
    }
}

// ---------------------------------------------------------------------------
// Iter 0: Uk = d/(d+1) * x ; Lam = 0 ; agg = 0
// ---------------------------------------------------------------------------
__global__ __launch_bounds__(256) void k_init(const float4* __restrict__ x,
                                              const float*  __restrict__ d) {
    int i = blockIdx.x * blockDim.x + threadIdx.x;
    if (i >= NODE_THREADS) return;
    int n = i >> 4;
    float dn = __ldg(&d[n]);
    float s = dn / (dn + 1.0f);
    float4 xv = __ldg(&x[i]);
    g_Uk[i] = make_float4(s * xv.x, s * xv.y, s * xv.z, s * xv.w);
    float4 z = make_float4(0.f, 0.f, 0.f, 0.f);
#pragma unroll
    for (int l = 0; l < 3; l++) g_Lam[l][i] = z;
    g_agg[i] = z;
}

// ---------------------------------------------------------------------------
// Fused: WU_l = W_l @ Uk (CSR gather, registers) -> Q/dual update ->
// tmp_l kept in registers -> CSC scatter of Sum_l W_l^T-col contribution
// into g_agg via RED.v4.  No g_tmp array at all.
// Thread (n, c): computes row n of WU/Q/Lam/tmp for feature chunk c, then
// scatters tmp[n] along column-n's edges (tmp producer == CSC owner).
// ---------------------------------------------------------------------------
__global__ __launch_bounds__(256) void k_wu_q_sc(const float* __restrict__ d,
                                                 float mu2, float inv_mu2, float mu2n) {
    int i = blockIdx.x * blockDim.x + threadIdx.x;
    if (i >= NODE_THREADS) return;
    int n = i >> 4;
    int c = i & 15;
    int rcnt  = g_rcnt[n];
    int rbase = n * STRIDE;

    // ---- CSR gather with 1-ahead prefetch ----
    float4 wu[LL];
#pragma unroll
    for (int l = 0; l < LL; l++) wu[l] = make_float4(0.f, 0.f, 0.f, 0.f);

    if (rcnt > 0) {
        int    col = g_csr_col[rbase];
        float4 wv  = g_csr_w[rbase];
        for (int k = 0; k < rcnt; k++) {
            int    coln = col;
            float4 wvn  = wv;
            if (k + 1 < rcnt) {
                coln = g_csr_col[rbase + k + 1];
                wvn  = g_csr_w[rbase + k + 1];
            }
            float4 u = g_Uk[col * F4 + c];
            wu[0].x += wv.x * u.x; wu[0].y += wv.x * u.y; wu[0].z += wv.x * u.z; wu[0].w += wv.x * u.w;
            wu[1].x += wv.y * u.x; wu[1].y += wv.y * u.y; wu[1].z += wv.y * u.z; wu[1].w += wv.y * u.w;
            wu[2].x += wv.z * u.x; wu[2].y += wv.z * u.y; wu[2].z += wv.z * u.z; wu[2].w += wv.z * u.w;
            wu[3].x += wv.w * u.x; wu[3].y += wv.w * u.y; wu[3].z += wv.w * u.z; wu[3].w += wv.w * u.w;
            col = coln; wv = wvn;
        }
    }

    // ---- Q / dual / tmp (tmp overwrites wu registers) ----
    // operator 0: nu=0 -> Q0 = WU0, Lam0 == 0, tmp0 = mu2n * WU0
    wu[0].x *= mu2n; wu[0].y *= mu2n; wu[0].z *= mu2n; wu[0].w *= mu2n;

    {
        const float nu_i[3] = {1.0f, 0.25f, 0.0625f};
        float dn = __ldg(&d[n]);
#pragma unroll
        for (int l = 0; l < 3; l++) {
            float4 wul = wu[l + 1];
            float4 lam = g_Lam[l][i];
            float eta = nu_i[l] * inv_mu2 * dn;
            float4 q, lam2;
            float xm;
            xm = wul.x - lam.x * inv_mu2;
            q.x = fmaxf(xm - eta, 0.f) - fmaxf(-xm - eta, 0.f);
            xm = wul.y - lam.y * inv_mu2;
            q.y = fmaxf(xm - eta, 0.f) - fmaxf(-xm - eta, 0.f);
            xm = wul.z - lam.z * inv_mu2;
            q.z = fmaxf(xm - eta, 0.f) - fmaxf(-xm - eta, 0.f);
            xm = wul.w - lam.w * inv_mu2;
            q.w = fmaxf(xm - eta, 0.f) - fmaxf(-xm - eta, 0.f);
            lam2.x = lam.x + mu2 * (q.x - wul.x);
            lam2.y = lam.y + mu2 * (q.y - wul.y);
            lam2.z = lam.z + mu2 * (q.z - wul.z);
            lam2.w = lam.w + mu2 * (q.w - wul.w);
            g_Lam[l][i] = lam2;
            wu[l + 1] = make_float4(mu2n * q.x + lam2.x,
                                    mu2n * q.y + lam2.y,
                                    mu2n * q.z + lam2.z,
                                    mu2n * q.w + lam2.w);
        }
    }

    // ---- CSC scatter: agg[r] += Sum_l W_l(r,n) * tmp_l[n] ----
    int ccnt  = g_ccnt[n];
    int cbase = n * STRIDE;
    if (ccnt > 0) {
        int    r  = g_csc_row[cbase];
        float4 wv = g_csc_w[cbase];
        for (int k = 0; k < ccnt; k++) {
            int    rn  = r;
            float4 wvn = wv;
            if (k + 1 < ccnt) {
                rn  = g_csc_row[cbase + k + 1];
                wvn = g_csc_w[cbase + k + 1];
            }
            float4 v;
            v.x = wv.x * wu[0].x + wv.y * wu[1].x + wv.z * wu[2].x + wv.w * wu[3].x;
            v.y = wv.x * wu[0].y + wv.y * wu[1].y + wv.z * wu[2].y + wv.w * wu[3].y;
            v.z = wv.x * wu[0].z + wv.y * wu[1].z + wv.z * wu[2].z + wv.w * wu[3].z;
            v.w = wv.x * wu[0].w + wv.y * wu[1].w + wv.z * wu[2].w + wv.w * wu[3].w;
            atomicAdd(&g_agg[r * F4 + c], v);     // RED.E.ADD.F32.V4
            r = rn; wv = wvn;
        }
    }
}

// ---------------------------------------------------------------------------
// U update: Uk = (d*x + agg)/(d + mu2); re-zeroes agg for the next scatter.
// ---------------------------------------------------------------------------
__global__ __launch_bounds__(256) void k_u(const float4* __restrict__ x,
                                           const float*  __restrict__ d,
                                           float mu2, float4* outp) {
    int i = blockIdx.x * blockDim.x + threadIdx.x;
    if (i >= NODE_THREADS) return;
    int n = i >> 4;
    float dn = __ldg(&d[n]);
    float s = 1.0f / (dn + mu2);
    float4 a  = g_agg[i];
    float4 xv = __ldg(&x[i]);
    float4 r = make_float4(s * (dn * xv.x + a.x),
                           s * (dn * xv.y + a.y),
                           s * (dn * xv.z + a.z),
                           s * (dn * xv.w + a.w));
    if (outp) outp[i] = r;
    else      g_Uk[i] = r;
    g_agg[i] = make_float4(0.f, 0.f, 0.f, 0.f);
}

// ---------------------------------------------------------------------------
extern "C" void kernel_launch(void* const* d_in, const int* in_sizes, int n_in,
                              void* d_out, int out_size) {
    const float4* x    = (const float4*)d_in[0];
    const float*  w    = (const float*) d_in[1];
    const float*  d    = (const float*) d_in[2];
    const int*    rows = (const int*)   d_in[3];
    const int*    cols = (const int*)   d_in[4];

    const float mu2s[6] = {1.0f, 1.1f, 1.21f, 1.331f, 1.4641f, 1.61051f};

    const int NB_NODE = (NODE_THREADS + 255) / 256;      // 3125
    const int NB_N    = (NN + 255) / 256;                // 196
    const int NB_E4   = (NNZ / 4 + 255) / 256;           // 782

    // ---- per-call CSR+CSC slab build ----
    k_zero   <<<NB_N, 256>>>();
    k_scatter<<<NB_E4, 256>>>(rows, cols, w);

    // ---- iteration 0 (closed-form U, then fused WU/Q/scatter) ----
    k_init   <<<NB_NODE, 256>>>(x, d);
    k_wu_q_sc<<<NB_NODE, 256>>>(d, mu2s[0], 1.0f / mu2s[0], mu2s[1]);

    // ---- iterations 1..4: U update, then fused pass (except after last) ----
    for (int it = 1; it < 5; it++) {
        bool fin = (it == 4);
        k_u<<<NB_NODE, 256>>>(x, d, mu2s[it], fin ? (float4*)d_out : (float4*)nullptr);
        if (!fin)
            k_wu_q_sc<<<NB_NODE, 256>>>(d, mu2s[it], 1.0f / mu2s[it], mu2s[it + 1]);
    }
}

// round 8
// speedup vs baseline: 1.4307x; 1.0435x over previous
#include <cuda_runtime.h>

#define NN   50000
#define FEAT 64
#define F4   16
#define LL   4
#define NNZ  800000
#define STRIDE 64                 // fixed slab per row/col (max degree guard)

#define NODE_THREADS (NN * F4)    // 800000

// ---------------- persistent scratch (rebuilt every call) ----------------
__device__ float4 g_Uk [NN * F4];
__device__ float4 g_Lam[3][NN * F4];     // operators 1..3 only (Lam0 == 0)
__device__ float4 g_agg[NN * F4];

__device__ int    g_rcnt[NN];
__device__ int    g_ccnt[NN];
__device__ int    g_csr_col[NN * STRIDE];
__device__ float4 g_csr_w  [NN * STRIDE];
__device__ int    g_csc_row[NN * STRIDE];
__device__ float4 g_csc_w  [NN * STRIDE];

// ---------------------------------------------------------------------------
// Setup
// ---------------------------------------------------------------------------
__global__ __launch_bounds__(256) void k_zero() {
    int i = blockIdx.x * blockDim.x + threadIdx.x;
    if (i < NN) { g_rcnt[i] = 0; g_ccnt[i] = 0; }
}

// 4 edges per thread: vectorized index/weight loads, deep atomic MLP.
__global__ __launch_bounds__(256) void k_scatter(const int*   __restrict__ rows,
                                                 const int*   __restrict__ cols,
                                                 const float* __restrict__ w) {
    int e4 = (blockIdx.x * blockDim.x + threadIdx.x) * 4;
    if (e4 >= NNZ) return;
    int4   r4 = *(const int4*)(rows + e4);
    int4   c4 = *(const int4*)(cols + e4);
    float4 a  = *(const float4*)(w + e4);              // l=0
    float4 b  = *(const float4*)(w + NNZ + e4);        // l=1
    float4 cc = *(const float4*)(w + 2 * NNZ + e4);    // l=2
    float4 dd = *(const float4*)(w + 3 * NNZ + e4);    // l=3

    int    rr[4] = {r4.x, r4.y, r4.z, r4.w};
    int    cl[4] = {c4.x, c4.y, c4.z, c4.w};
    float4 w4[4] = {make_float4(a.x, b.x, cc.x, dd.x),
                    make_float4(a.y, b.y, cc.y, dd.y),
                    make_float4(a.z, b.z, cc.z, dd.z),
                    make_float4(a.w, b.w, cc.w, dd.w)};
#pragma unroll
    for (int j = 0; j < 4; j++) {
        int p = atomicAdd(&g_rcnt[rr[j]], 1);
        if (p < STRIDE) {
            g_csr_col[rr[j] * STRIDE + p] = cl[j];
            g_csr_w  [rr[j] * STRIDE + p] = w4[j];
        }
        int q = atomicAdd(&g_ccnt[cl[j]], 1);
        if (q < STRIDE) {
            g_csc_row[cl[j] * STRIDE + q] = rr[j];
            g_csc_w  [cl[j] * STRIDE + q] = w4[j];
        }
    }
}

// ---------------------------------------------------------------------------
// Pad slabs to a multiple of 4 with self-referencing zero-weight edges
// (col=row=n so pad REDs spread across nodes, never hot-spotting one addr).
// Overwrites counts with the rounded-up values.
// ---------------------------------------------------------------------------
__global__ __launch_bounds__(256) void k_pad() {
    int n = blockIdx.x * blockDim.x + threadIdx.x;
    if (n >= NN) return;
    float4 z = make_float4(0.f, 0.f, 0.f, 0.f);
    int rc  = g_rcnt[n];
    int rc4 = (rc + 3) & ~3;
    for (int k = rc; k < rc4; k++) {
        g_csr_col[n * STRIDE + k] = n;
        g_csr_w  [n * STRIDE + k] = z;
    }
    g_rcnt[n] = rc4;
    int cc  = g_ccnt[n];
    int cc4 = (cc + 3) & ~3;
    for (int k = cc; k < cc4; k++) {
        g_csc_row[n * STRIDE + k] = n;
        g_csc_w  [n * STRIDE + k] = z;
    }
    g_ccnt[n] = cc4;
}

// ---------------------------------------------------------------------------
// Iter 0: Uk = d/(d+1) * x ; Lam = 0 ; agg = 0
// ---------------------------------------------------------------------------
__global__ __launch_bounds__(256) void k_init(const float4* __restrict__ x,
                                              const float*  __restrict__ d) {
    int i = blockIdx.x * blockDim.x + threadIdx.x;
    if (i >= NODE_THREADS) return;
    int n = i >> 4;
    float dn = __ldg(&d[n]);
    float s = dn / (dn + 1.0f);
    float4 xv = __ldg(&x[i]);
    g_Uk[i] = make_float4(s * xv.x, s * xv.y, s * xv.z, s * xv.w);
    float4 z = make_float4(0.f, 0.f, 0.f, 0.f);
#pragma unroll
    for (int l = 0; l < 3; l++) g_Lam[l][i] = z;
    g_agg[i] = z;
}

// ---------------------------------------------------------------------------
// Fused: WU = W@Uk (CSR gather, branch-free unroll-4) -> Q/dual in regs ->
// CSC scatter of tmp into g_agg via RED.v4.  No g_tmp array.
// ---------------------------------------------------------------------------
__global__ __launch_bounds__(256, 5) void k_wu_q_sc(const float* __restrict__ d,
                                                    float mu2, float inv_mu2, float mu2n) {
    int i = blockIdx.x * blockDim.x + threadIdx.x;
    if (i >= NODE_THREADS) return;
    int n = i >> 4;
    int c = i & 15;
    int rcnt  = g_rcnt[n];          // multiple of 4
    int rbase = n * STRIDE;

    float4 wu[LL];
#pragma unroll
    for (int l = 0; l < LL; l++) wu[l] = make_float4(0.f, 0.f, 0.f, 0.f);

    // ---- CSR gather: 4 edges per trip, all loads independent ----
    for (int k = 0; k < rcnt; k += 4) {
        int4   c4 = *(const int4*)&g_csr_col[rbase + k];
        float4 w0 = g_csr_w[rbase + k];
        float4 w1 = g_csr_w[rbase + k + 1];
        float4 w2 = g_csr_w[rbase + k + 2];
        float4 w3 = g_csr_w[rbase + k + 3];
        float4 u0 = g_Uk[c4.x * F4 + c];
        float4 u1 = g_Uk[c4.y * F4 + c];
        float4 u2 = g_Uk[c4.z * F4 + c];
        float4 u3 = g_Uk[c4.w * F4 + c];
#define ACC(W, U)                                                           \
        wu[0].x += (W).x * (U).x; wu[0].y += (W).x * (U).y;                 \
        wu[0].z += (W).x * (U).z; wu[0].w += (W).x * (U).w;                 \
        wu[1].x += (W).y * (U).x; wu[1].y += (W).y * (U).y;                 \
        wu[1].z += (W).y * (U).z; wu[1].w += (W).y * (U).w;                 \
        wu[2].x += (W).z * (U).x; wu[2].y += (W).z * (U).y;                 \
        wu[2].z += (W).z * (U).z; wu[2].w += (W).z * (U).w;                 \
        wu[3].x += (W).w * (U).x; wu[3].y += (W).w * (U).y;                 \
        wu[3].z += (W).w * (U).z; wu[3].w += (W).w * (U).w;
        ACC(w0, u0) ACC(w1, u1) ACC(w2, u2) ACC(w3, u3)
#undef ACC
    }

    // ---- Q / dual / tmp (tmp overwrites wu registers) ----
    // operator 0: nu=0 -> Q0 = WU0, Lam0 == 0, tmp0 = mu2n * WU0
    wu[0].x *= mu2n; wu[0].y *= mu2n; wu[0].z *= mu2n; wu[0].w *= mu2n;
    {
        const float nu_i[3] = {1.0f, 0.25f, 0.0625f};
        float dn = __ldg(&d[n]);
#pragma unroll
        for (int l = 0; l < 3; l++) {
            float4 wul = wu[l + 1];
            float4 lam = g_Lam[l][i];
            float eta = nu_i[l] * inv_mu2 * dn;
            float4 q, lam2;
            float xm;
            xm = wul.x - lam.x * inv_mu2;
            q.x = fmaxf(xm - eta, 0.f) - fmaxf(-xm - eta, 0.f);
            xm = wul.y - lam.y * inv_mu2;
            q.y = fmaxf(xm - eta, 0.f) - fmaxf(-xm - eta, 0.f);
            xm = wul.z - lam.z * inv_mu2;
            q.z = fmaxf(xm - eta, 0.f) - fmaxf(-xm - eta, 0.f);
            xm = wul.w - lam.w * inv_mu2;
            q.w = fmaxf(xm - eta, 0.f) - fmaxf(-xm - eta, 0.f);
            lam2.x = lam.x + mu2 * (q.x - wul.x);
            lam2.y = lam.y + mu2 * (q.y - wul.y);
            lam2.z = lam.z + mu2 * (q.z - wul.z);
            lam2.w = lam.w + mu2 * (q.w - wul.w);
            g_Lam[l][i] = lam2;
            wu[l + 1] = make_float4(mu2n * q.x + lam2.x,
                                    mu2n * q.y + lam2.y,
                                    mu2n * q.z + lam2.z,
                                    mu2n * q.w + lam2.w);
        }
    }

    // ---- CSC scatter: 4 edges per trip, branch-free, batched REDs ----
    int ccnt  = g_ccnt[n];          // multiple of 4
    int cbase = n * STRIDE;
    for (int k = 0; k < ccnt; k += 4) {
        int4   r4 = *(const int4*)&g_csc_row[cbase + k];
        float4 w0 = g_csc_w[cbase + k];
        float4 w1 = g_csc_w[cbase + k + 1];
        float4 w2 = g_csc_w[cbase + k + 2];
        float4 w3 = g_csc_w[cbase + k + 3];
#define SCT(W, R)                                                           \
        {                                                                   \
            float4 v;                                                       \
            v.x = (W).x * wu[0].x + (W).y * wu[1].x + (W).z * wu[2].x + (W).w * wu[3].x; \
            v.y = (W).x * wu[0].y + (W).y * wu[1].y + (W).z * wu[2].y + (W).w * wu[3].y; \
            v.z = (W).x * wu[0].z + (W).y * wu[1].z + (W).z * wu[2].z + (W).w * wu[3].z; \
            v.w = (W).x * wu[0].w + (W).y * wu[1].w + (W).z * wu[2].w + (W).w * wu[3].w; \
            atomicAdd(&g_agg[(R) * F4 + c], v);                             \
        }
        SCT(w0, r4.x) SCT(w1, r4.y) SCT(w2, r4.z) SCT(w3, r4.w)
#undef SCT
    }
}

// ---------------------------------------------------------------------------
// U update: Uk = (d*x + agg)/(d + mu2); re-zeroes agg for the next scatter.
// ---------------------------------------------------------------------------
__global__ __launch_bounds__(256) void k_u(const float4* __restrict__ x,
                                           const float*  __restrict__ d,
                                           float mu2, float4* outp) {
    int i = blockIdx.x * blockDim.x + threadIdx.x;
    if (i >= NODE_THREADS) return;
    int n = i >> 4;
    float dn = __ldg(&d[n]);
    float s = 1.0f / (dn + mu2);
    float4 a  = g_agg[i];
    float4 xv = __ldg(&x[i]);
    float4 r = make_float4(s * (dn * xv.x + a.x),
                           s * (dn * xv.y + a.y),
                           s * (dn * xv.z + a.z),
                           s * (dn * xv.w + a.w));
    if (outp) outp[i] = r;
    else      g_Uk[i] = r;
    g_agg[i] = make_float4(0.f, 0.f, 0.f, 0.f);
}

// ---------------------------------------------------------------------------
extern "C" void kernel_launch(void* const* d_in, const int* in_sizes, int n_in,
                              void* d_out, int out_size) {
    const float4* x    = (const float4*)d_in[0];
    const float*  w    = (const float*) d_in[1];
    const float*  d    = (const float*) d_in[2];
    const int*    rows = (const int*)   d_in[3];
    const int*    cols = (const int*)   d_in[4];

    const float mu2s[6] = {1.0f, 1.1f, 1.21f, 1.331f, 1.4641f, 1.61051f};

    const int NB_NODE = (NODE_THREADS + 255) / 256;      // 3125
    const int NB_N    = (NN + 255) / 256;                // 196
    const int NB_E4   = (NNZ / 4 + 255) / 256;           // 782

    // ---- per-call CSR+CSC slab build, then pad to multiple of 4 ----
    k_zero   <<<NB_N, 256>>>();
    k_scatter<<<NB_E4, 256>>>(rows, cols, w);
    k_pad    <<<NB_N, 256>>>();

    // ---- iteration 0 (closed-form U, then fused WU/Q/scatter) ----
    k_init   <<<NB_NODE, 256>>>(x, d);
    k_wu_q_sc<<<NB_NODE, 256>>>(d, mu2s[0], 1.0f / mu2s[0], mu2s[1]);

    // ---- iterations 1..4: U update, then fused pass (except after last) ----
    for (int it = 1; it < 5; it++) {
        bool fin = (it == 4);
        k_u<<<NB_NODE, 256>>>(x, d, mu2s[it], fin ? (float4*)d_out : (float4*)nullptr);
        if (!fin)
            k_wu_q_sc<<<NB_NODE, 256>>>(d, mu2s[it], 1.0f / mu2s[it], mu2s[it + 1]);
    }
}